// round 3
// baseline (speedup 1.0000x reference)
#include <cuda_runtime.h>

#define IDFn 128
#define CDFn 256
#define Bn   16
#define Qn   16384
#define SLn  48

// Scratch (no cudaMalloc allowed) — device globals.
__device__ __align__(16) float g_srcT[Bn * IDFn * SLn];   // [b][i][s]
__device__ __align__(16) float g_sent[Bn * IDFn];         // [b][o]
__device__ __align__(16) float g_maskF[Bn * SLn];         // 1.0 = masked

// ---------------- packed fp32x2 helpers ----------------
static __device__ __forceinline__ unsigned long long fma2(unsigned long long a,
                                                          unsigned long long b,
                                                          unsigned long long c) {
    unsigned long long d;
    asm("fma.rn.f32x2 %0, %1, %2, %3;" : "=l"(d) : "l"(a), "l"(b), "l"(c));
    return d;
}
static __device__ __forceinline__ unsigned long long pack2(float x, float y) {
    unsigned long long d;
    asm("mov.b64 %0, {%1, %2};" : "=l"(d) : "f"(x), "f"(y));
    return d;
}
static __device__ __forceinline__ float2 unpack2(unsigned long long v) {
    float2 r;
    asm("mov.b64 {%0, %1}, %2;" : "=f"(r.x), "=f"(r.y) : "l"(v));
    return r;
}

// ---------------- mask dtype detection + conversion ----------------
// mask is logically bool[16][48]; the harness may hand it to us as u8, i32 or
// f32. Detect from byte patterns in the first 768 bytes (present in all three
// layouts), then materialize as float 0/1 into g_maskF.
//   f32 1.0f = {0,0,0x80,0x3f}  -> any 0x3f/0x80 byte => f32
//   i32 0/1  = {v,0,0,0}        -> all bytes at idx%4!=0 are 0 => i32
//   u8  0/1  -> otherwise
__global__ void prep_mask_kernel(const unsigned char* __restrict__ mraw) {
    __shared__ int cnt_f32, cnt_nz3;
    int tid = threadIdx.x;                 // 768 threads
    if (tid == 0) { cnt_f32 = 0; cnt_nz3 = 0; }
    __syncthreads();
    unsigned char v = mraw[tid];
    if (v == 0x3f || v == 0x80) atomicAdd(&cnt_f32, 1);
    if ((tid & 3) != 0 && v != 0) atomicAdd(&cnt_nz3, 1);
    __syncthreads();
    float f;
    if (cnt_f32 > 0) {
        f = (((const float*)mraw)[tid] != 0.0f) ? 1.0f : 0.0f;
    } else if (cnt_nz3 == 0) {
        f = ((const int*)mraw)[tid] ? 1.0f : 0.0f;
    } else {
        f = v ? 1.0f : 0.0f;
    }
    g_maskF[tid] = f;
}

// ---------------- prologue: sourceT = w_ctx @ context ----------------
// srcT[b][i][s] = sum_c w_ctx[i][c] * context[b][c][s]
__global__ void prep_srcT_kernel(const float* __restrict__ context,
                                 const float* __restrict__ w_ctx) {
    int idx = blockIdx.x * 256 + threadIdx.x;            // < 16*128*48
    int s = idx % SLn;
    int t = idx / SLn;
    int i = t % IDFn;
    int b = t / IDFn;
    const float* wr = w_ctx + i * CDFn;
    const float* cb = context + (b * CDFn) * SLn + s;
    float acc = 0.0f;
#pragma unroll 8
    for (int c = 0; c < CDFn; c++) acc = fmaf(wr[c], cb[c * SLn], acc);
    g_srcT[idx] = acc;
}

// ---------------- prologue: sent = sentence @ w_lin^T + b_lin ----------------
__global__ void prep_sent_kernel(const float* __restrict__ sentence,
                                 const float* __restrict__ w_lin,
                                 const float* __restrict__ b_lin) {
    int idx = blockIdx.x * 256 + threadIdx.x;            // < 16*128
    int o = idx % IDFn;
    int b = idx / IDFn;
    float acc = b_lin[o];
    const float* sb = sentence + b * 100;
    const float* wr = w_lin + o * 100;
#pragma unroll 4
    for (int j = 0; j < 100; j++) acc = fmaf(sb[j], wr[j], acc);
    g_sent[idx] = acc;
}

// ---------------- fused attention: logits -> mask -> softmax -> WC + WA -------
// Each thread owns 2 q positions fully. accs are 24 f32x2 (48 s-slots) per q.
static __device__ __forceinline__ void softmax_store(unsigned long long* a,
                                                     const float* mS,
                                                     float* wa_base /* + q */) {
    const float NEGINF = __int_as_float(0xff800000);
    float M = -3.0e38f;
#pragma unroll
    for (int j = 0; j < 24; j++) {
        float2 v = unpack2(a[j]);
        if (mS[2 * j]     != 0.0f) v.x = NEGINF;
        if (mS[2 * j + 1] != 0.0f) v.y = NEGINF;
        a[j] = pack2(v.x, v.y);
        M = fmaxf(M, fmaxf(v.x, v.y));
    }
    float S = 0.0f;
#pragma unroll
    for (int j = 0; j < 24; j++) {
        float2 v = unpack2(a[j]);
        float e0 = __expf(v.x - M);
        float e1 = __expf(v.y - M);
        S += e0 + e1;
        a[j] = pack2(e0, e1);
    }
    float r = 1.0f / S;
#pragma unroll
    for (int j = 0; j < 24; j++) {
        float2 v = unpack2(a[j]);
        float p0 = v.x * r;
        float p1 = v.y * r;
        wa_base[(2 * j) * Qn]     = p0;
        wa_base[(2 * j + 1) * Qn] = p1;
        a[j] = pack2(p0, p1);
    }
}

__global__ void __launch_bounds__(256)
attn_kernel(const float* __restrict__ input,
            float* __restrict__ wc,
            float* __restrict__ wa) {
    __shared__ unsigned long long sT[IDFn * 24];   // srcT rows as f32x2 pairs
    __shared__ float mS[SLn];

    const int b = blockIdx.y;
    const int tid = threadIdx.x;

    const unsigned long long* sg =
        (const unsigned long long*)(g_srcT + b * IDFn * SLn);
#pragma unroll
    for (int k = 0; k < 12; k++) sT[tid + k * 256] = sg[tid + k * 256];
    if (tid < SLn) mS[tid] = g_maskF[b * SLn + tid];
    __syncthreads();

    const int q0 = blockIdx.x * 512 + tid;
    const int q1 = q0 + 256;
    const float* inb = input + (size_t)b * IDFn * Qn;

    unsigned long long a0[24], a1[24];
#pragma unroll
    for (int j = 0; j < 24; j++) { a0[j] = 0ULL; a1[j] = 0ULL; }

    // Phase A: logits[q][s] = sum_i target[i][q] * srcT[i][s]
#pragma unroll 2
    for (int i = 0; i < 128; i++) {
        float t0 = inb[i * Qn + q0];
        float t1 = inb[i * Qn + q1];
        unsigned long long t0d = pack2(t0, t0);
        unsigned long long t1d = pack2(t1, t1);
        const unsigned long long* row = &sT[i * 24];
#pragma unroll
        for (int j = 0; j < 24; j++) {
            unsigned long long w = row[j];
            a0[j] = fma2(w, t0d, a0[j]);
            a1[j] = fma2(w, t1d, a1[j]);
        }
    }

    float* wab = wa + (size_t)b * SLn * Qn;
    softmax_store(a0, mS, wab + q0);
    softmax_store(a1, mS, wab + q1);

    // Phase B: wc[i][q] = sum_s srcT[i][s] * p[q][s]
    float* wcb = wc + (size_t)b * IDFn * Qn;
#pragma unroll 2
    for (int i = 0; i < 128; i++) {
        const unsigned long long* row = &sT[i * 24];
        unsigned long long s0a = 0ULL, s0b = 0ULL, s1a = 0ULL, s1b = 0ULL;
#pragma unroll
        for (int j = 0; j < 24; j += 2) {
            s0a = fma2(row[j],     a0[j],     s0a);
            s0b = fma2(row[j + 1], a0[j + 1], s0b);
            s1a = fma2(row[j],     a1[j],     s1a);
            s1b = fma2(row[j + 1], a1[j + 1], s1b);
        }
        float2 u0a = unpack2(s0a), u0b = unpack2(s0b);
        float2 u1a = unpack2(s1a), u1b = unpack2(s1b);
        wcb[i * Qn + q0] = (u0a.x + u0a.y) + (u0b.x + u0b.y);
        wcb[i * Qn + q1] = (u1a.x + u1a.y) + (u1b.x + u1b.y);
    }
}

// ---------------- fused sentence path (PERSISTENT) ----------------
// Y[o][q] = sum_i wT[i][o] * x[i][q],  x = input * sent  -> softmax over o
// Grid = 152 persistent blocks; w_sv transposed to smem ONCE per block;
// grid-stride loop over 2048 tiles of TQ=128 q.
// Warp w owns q = w*16 .. w*16+15 ; within the warp, half-warp g = lane>>4
// takes q-subgroup g*8..g*8+7 ; lane&15 owns 8 output channels (l&15)*8..+7.
// acc = 8q x 8o = 32 f32x2 regs/thread.
#define TQ 128
#define WT_ULL   (IDFn * 66)                 // 66-ull padded rows of wT
#define XS_ULL   (IDFn * TQ)                 // x duplicated as f32x2
#define SENT_SMEM_BYTES ((WT_ULL + XS_ULL) * 8 + IDFn * 4)
#define SA_PAD 129                           // float staging pad (reuses xs2)

__global__ void __launch_bounds__(256, 1)
sent_kernel(const float* __restrict__ input,
            const float* __restrict__ w_sv,
            float* __restrict__ ws,
            float* __restrict__ sa) {
    extern __shared__ unsigned long long smemU[];
    unsigned long long* wT  = smemU;                       // [128][66] ull
    unsigned long long* xs2 = smemU + WT_ULL;              // [128][TQ] ull
    float* saS   = (float*)xs2;                            // staging (reuse)
    float* sentS = (float*)(smemU + WT_ULL + XS_ULL);      // [128]

    const int tid = threadIdx.x;
    const int w = tid >> 5, lane = tid & 31;
    const int hl = lane & 15, g = lane >> 4;
    const int obase = hl * 8;
    const int qw = w * 16 + g * 8;           // this thread's first q in tile

    // transpose w_sv[o][i] -> wT row i (132-float padded rows), once per block
    for (int idx = tid; idx < IDFn * IDFn; idx += 256) {
        int o = idx >> 7, i = idx & 127;
        ((float*)wT)[i * 132 + o] = w_sv[idx];
    }

    const int ntiles = Bn * (Qn / TQ);       // 2048
    for (int t = blockIdx.x; t < ntiles; t += gridDim.x) {
        const int b = t >> 7;
        const int qbase = (t & 127) * TQ;

        if (tid < IDFn) sentS[tid] = g_sent[b * IDFn + tid];
        __syncthreads();                      // wT + sentS ready; prev tile done

        const float* inb = input + (size_t)b * IDFn * Qn + qbase;
        for (int idx = tid; idx < IDFn * TQ; idx += 256) {
            int i = idx >> 7, qq = idx & (TQ - 1);
            float v = inb[i * Qn + qq] * sentS[i];
            xs2[idx] = pack2(v, v);
        }
        __syncthreads();

        unsigned long long acc[8][4];
#pragma unroll
        for (int k = 0; k < 8; k++)
#pragma unroll
            for (int j = 0; j < 4; j++) acc[k][j] = 0ULL;

#pragma unroll 2
        for (int i = 0; i < IDFn; i++) {
            ulonglong2 wv0 = *(const ulonglong2*)&wT[i * 66 + hl * 4];
            ulonglong2 wv1 = *(const ulonglong2*)&wT[i * 66 + hl * 4 + 2];
            const unsigned long long* xr = &xs2[i * TQ + qw];
#pragma unroll
            for (int k = 0; k < 8; k++) {
                unsigned long long x = xr[k];
                acc[k][0] = fma2(wv0.x, x, acc[k][0]);
                acc[k][1] = fma2(wv0.y, x, acc[k][1]);
                acc[k][2] = fma2(wv1.x, x, acc[k][2]);
                acc[k][3] = fma2(wv1.y, x, acc[k][3]);
            }
        }
        __syncthreads();                      // all xs2 reads done -> reuse as saS

        // channel softmax per q (128 o spread over the 16-lane half-warp)
#pragma unroll
        for (int k = 0; k < 8; k++) {
            float2 v0 = unpack2(acc[k][0]);
            float2 v1 = unpack2(acc[k][1]);
            float2 v2 = unpack2(acc[k][2]);
            float2 v3 = unpack2(acc[k][3]);
            float m = fmaxf(fmaxf(fmaxf(v0.x, v0.y), fmaxf(v1.x, v1.y)),
                            fmaxf(fmaxf(v2.x, v2.y), fmaxf(v3.x, v3.y)));
#pragma unroll
            for (int off = 8; off; off >>= 1)
                m = fmaxf(m, __shfl_xor_sync(0xffffffffu, m, off));
            float e0 = __expf(v0.x - m), e1 = __expf(v0.y - m);
            float e2 = __expf(v1.x - m), e3 = __expf(v1.y - m);
            float e4 = __expf(v2.x - m), e5 = __expf(v2.y - m);
            float e6 = __expf(v3.x - m), e7 = __expf(v3.y - m);
            float s = ((e0 + e1) + (e2 + e3)) + ((e4 + e5) + (e6 + e7));
#pragma unroll
            for (int off = 8; off; off >>= 1)
                s += __shfl_xor_sync(0xffffffffu, s, off);
            float r = 1.0f / s;
            int qq = qw + k;
            saS[(obase + 0) * SA_PAD + qq] = e0 * r;
            saS[(obase + 1) * SA_PAD + qq] = e1 * r;
            saS[(obase + 2) * SA_PAD + qq] = e2 * r;
            saS[(obase + 3) * SA_PAD + qq] = e3 * r;
            saS[(obase + 4) * SA_PAD + qq] = e4 * r;
            saS[(obase + 5) * SA_PAD + qq] = e5 * r;
            saS[(obase + 6) * SA_PAD + qq] = e6 * r;
            saS[(obase + 7) * SA_PAD + qq] = e7 * r;
        }
        __syncthreads();

        // coalesced epilogue: 128 consecutive q per channel row
        float* sab = sa + (size_t)b * IDFn * Qn + qbase;
        float* wsb = ws + (size_t)b * IDFn * Qn + qbase;
        for (int idx = tid; idx < IDFn * TQ; idx += 256) {
            int o = idx >> 7, qq = idx & (TQ - 1);
            float v = saS[o * SA_PAD + qq];
            sab[o * Qn + qq] = v;
            wsb[o * Qn + qq] = sentS[o] * v;
        }
        __syncthreads();                      // protect sentS/saS for next tile
    }
}

// ---------------- launch ----------------
extern "C" void kernel_launch(void* const* d_in, const int* in_sizes, int n_in,
                              void* d_out, int out_size) {
    const float*         input    = (const float*)d_in[0];
    const float*         sentence = (const float*)d_in[1];
    const float*         context  = (const float*)d_in[2];
    const unsigned char* mask     = (const unsigned char*)d_in[3];
    const float*         w_ctx    = (const float*)d_in[4];
    const float*         w_sv     = (const float*)d_in[5];
    const float*         w_lin    = (const float*)d_in[6];
    const float*         b_lin    = (const float*)d_in[7];

    float* out = (float*)d_out;
    float* wc = out;                                    // (B,128,128,128)
    float* ws = out + (size_t)Bn * IDFn * Qn;           // (B,128,128,128)
    float* wa = ws + (size_t)Bn * IDFn * Qn;            // (B,48,128,128)
    float* sa = wa + (size_t)Bn * SLn * Qn;             // (B,128,128,128)

    prep_mask_kernel<<<1, Bn * SLn>>>(mask);
    prep_srcT_kernel<<<(Bn * IDFn * SLn) / 256, 256>>>(context, w_ctx);
    prep_sent_kernel<<<(Bn * IDFn) / 256, 256>>>(sentence, w_lin, b_lin);

    attn_kernel<<<dim3(Qn / 512, Bn), 256>>>(input, wc, wa);

    cudaFuncSetAttribute(sent_kernel,
                         cudaFuncAttributeMaxDynamicSharedMemorySize,
                         SENT_SMEM_BYTES);
    sent_kernel<<<152, 256, SENT_SMEM_BYTES>>>(input, w_sv, ws, sa);
}

// round 5
// speedup vs baseline: 1.4690x; 1.4690x over previous
#include <cuda_runtime.h>

#define IDFn 128
#define CDFn 256
#define Bn   16
#define Qn   16384
#define SLn  48

// Scratch (no cudaMalloc allowed) — device globals.
__device__ __align__(16) float g_srcT[Bn * IDFn * SLn];   // [b][i][s]
__device__ __align__(16) float g_sent[Bn * IDFn];         // [b][o]
__device__ __align__(16) float g_maskF[Bn * SLn];         // 1.0 = masked

// ---------------- packed fp32x2 helpers ----------------
static __device__ __forceinline__ unsigned long long fma2(unsigned long long a,
                                                          unsigned long long b,
                                                          unsigned long long c) {
    unsigned long long d;
    asm("fma.rn.f32x2 %0, %1, %2, %3;" : "=l"(d) : "l"(a), "l"(b), "l"(c));
    return d;
}
static __device__ __forceinline__ unsigned long long pack2(float x, float y) {
    unsigned long long d;
    asm("mov.b64 %0, {%1, %2};" : "=l"(d) : "f"(x), "f"(y));
    return d;
}
static __device__ __forceinline__ float2 unpack2(unsigned long long v) {
    float2 r;
    asm("mov.b64 {%0, %1}, %2;" : "=f"(r.x), "=f"(r.y) : "l"(v));
    return r;
}
static __device__ __forceinline__ void cpasync16(void* sdst, const void* gsrc) {
    unsigned int sa = (unsigned int)__cvta_generic_to_shared(sdst);
    asm volatile("cp.async.cg.shared.global [%0], [%1], 16;" :: "r"(sa), "l"(gsrc));
}
#define CP_COMMIT() asm volatile("cp.async.commit_group;")
#define CP_WAIT1()  asm volatile("cp.async.wait_group 1;")
#define CP_WAIT0()  asm volatile("cp.async.wait_group 0;")

// ---------------- mask dtype detection + conversion ----------------
__global__ void prep_mask_kernel(const unsigned char* __restrict__ mraw) {
    __shared__ int cnt_f32, cnt_nz3;
    int tid = threadIdx.x;                 // 768 threads
    if (tid == 0) { cnt_f32 = 0; cnt_nz3 = 0; }
    __syncthreads();
    unsigned char v = mraw[tid];
    if (v == 0x3f || v == 0x80) atomicAdd(&cnt_f32, 1);
    if ((tid & 3) != 0 && v != 0) atomicAdd(&cnt_nz3, 1);
    __syncthreads();
    float f;
    if (cnt_f32 > 0) {
        f = (((const float*)mraw)[tid] != 0.0f) ? 1.0f : 0.0f;
    } else if (cnt_nz3 == 0) {
        f = ((const int*)mraw)[tid] ? 1.0f : 0.0f;
    } else {
        f = v ? 1.0f : 0.0f;
    }
    g_maskF[tid] = f;
}

// ---------------- prologue: sourceT = w_ctx @ context ----------------
__global__ void prep_srcT_kernel(const float* __restrict__ context,
                                 const float* __restrict__ w_ctx) {
    int idx = blockIdx.x * 256 + threadIdx.x;            // < 16*128*48
    int s = idx % SLn;
    int t = idx / SLn;
    int i = t % IDFn;
    int b = t / IDFn;
    const float* wr = w_ctx + i * CDFn;
    const float* cb = context + (b * CDFn) * SLn + s;
    float acc = 0.0f;
#pragma unroll 8
    for (int c = 0; c < CDFn; c++) acc = fmaf(wr[c], cb[c * SLn], acc);
    g_srcT[idx] = acc;
}

// ---------------- prologue: sent = sentence @ w_lin^T + b_lin ----------------
__global__ void prep_sent_kernel(const float* __restrict__ sentence,
                                 const float* __restrict__ w_lin,
                                 const float* __restrict__ b_lin) {
    int idx = blockIdx.x * 256 + threadIdx.x;            // < 16*128
    int o = idx % IDFn;
    int b = idx / IDFn;
    float acc = b_lin[o];
    const float* sb = sentence + b * 100;
    const float* wr = w_lin + o * 100;
#pragma unroll 4
    for (int j = 0; j < 100; j++) acc = fmaf(sb[j], wr[j], acc);
    g_sent[idx] = acc;
}

// ---------------- fused attention with cp.async input pipeline ----------------
#define ACHUNK 8
#define ASMEM_BYTES (IDFn * 24 * 8 + 256 + 2 * ACHUNK * 512 * 4)  // 57600

static __device__ __forceinline__ void softmax_store(unsigned long long* a,
                                                     const float* mS,
                                                     float* wa_base /* + q */) {
    const float NEGINF = __int_as_float(0xff800000);
    float M = -3.0e38f;
#pragma unroll
    for (int j = 0; j < 24; j++) {
        float2 v = unpack2(a[j]);
        if (mS[2 * j]     != 0.0f) v.x = NEGINF;
        if (mS[2 * j + 1] != 0.0f) v.y = NEGINF;
        a[j] = pack2(v.x, v.y);
        M = fmaxf(M, fmaxf(v.x, v.y));
    }
    float S = 0.0f;
#pragma unroll
    for (int j = 0; j < 24; j++) {
        float2 v = unpack2(a[j]);
        float e0 = __expf(v.x - M);
        float e1 = __expf(v.y - M);
        S += e0 + e1;
        a[j] = pack2(e0, e1);
    }
    float r = 1.0f / S;
#pragma unroll
    for (int j = 0; j < 24; j++) {
        float2 v = unpack2(a[j]);
        float p0 = v.x * r;
        float p1 = v.y * r;
        wa_base[(2 * j) * Qn]     = p0;
        wa_base[(2 * j + 1) * Qn] = p1;
        a[j] = pack2(p0, p1);
    }
}

__global__ void __launch_bounds__(256)
attn_kernel(const float* __restrict__ input,
            float* __restrict__ wc,
            float* __restrict__ wa) {
    extern __shared__ unsigned long long dynA[];
    unsigned long long* sT = dynA;                 // [128*24] ull
    float* mS  = (float*)(dynA + IDFn * 24);       // 64 floats (48 used)
    float* sIn = mS + 64;                          // [2][8][512] floats

    const int b = blockIdx.y;
    const int tid = threadIdx.x;
    const int qblk = blockIdx.x * 512;

    const unsigned long long* sg =
        (const unsigned long long*)(g_srcT + b * IDFn * SLn);
#pragma unroll
    for (int k = 0; k < 12; k++) sT[tid + k * 256] = sg[tid + k * 256];
    if (tid < SLn) mS[tid] = g_maskF[b * SLn + tid];

    const float* inb = input + (size_t)b * IDFn * Qn + qblk;

    // chunk kicker: 8 rows x 512 floats = 16KB, 4 x 16B per thread
    auto kick = [&](int c) {
        int buf = c & 1;
#pragma unroll
        for (int j = 0; j < 4; j++) {
            int idx = j * 256 + tid;
            int r = idx >> 7, col = idx & 127;
            cpasync16(&sIn[buf * (ACHUNK * 512) + r * 512 + col * 4],
                      inb + (c * ACHUNK + r) * Qn + col * 4);
        }
        CP_COMMIT();
    };

    kick(0);

    unsigned long long a0[24], a1[24];
#pragma unroll
    for (int j = 0; j < 24; j++) { a0[j] = 0ULL; a1[j] = 0ULL; }

    // Phase A: logits[q][s] = sum_i target[i][q] * srcT[i][s]
    for (int c = 0; c < 16; c++) {
        if (c < 15) { kick(c + 1); CP_WAIT1(); }
        else        { CP_WAIT0(); }
        __syncthreads();
        const float* xb = sIn + (c & 1) * (ACHUNK * 512);
#pragma unroll
        for (int r = 0; r < ACHUNK; r++) {
            const int i = c * ACHUNK + r;
            float t0 = xb[r * 512 + tid];
            float t1 = xb[r * 512 + tid + 256];
            unsigned long long t0d = pack2(t0, t0);
            unsigned long long t1d = pack2(t1, t1);
            const unsigned long long* row = &sT[i * 24];
#pragma unroll
            for (int j = 0; j < 12; j++) {
                ulonglong2 wv = *(const ulonglong2*)&row[j * 2];
                a0[2 * j]     = fma2(wv.x, t0d, a0[2 * j]);
                a0[2 * j + 1] = fma2(wv.y, t0d, a0[2 * j + 1]);
                a1[2 * j]     = fma2(wv.x, t1d, a1[2 * j]);
                a1[2 * j + 1] = fma2(wv.y, t1d, a1[2 * j + 1]);
            }
        }
        __syncthreads();
    }

    const int q0 = qblk + tid;
    const int q1 = q0 + 256;
    float* wab = wa + (size_t)b * SLn * Qn;
    softmax_store(a0, mS, wab + q0);
    softmax_store(a1, mS, wab + q1);

    // Phase B: wc[i][q] = sum_s srcT[i][s] * p[q][s]
    float* wcb = wc + (size_t)b * IDFn * Qn;
#pragma unroll 2
    for (int i = 0; i < 128; i++) {
        const unsigned long long* row = &sT[i * 24];
        unsigned long long s0a = 0ULL, s0b = 0ULL, s1a = 0ULL, s1b = 0ULL;
#pragma unroll
        for (int j = 0; j < 12; j++) {
            ulonglong2 wv = *(const ulonglong2*)&row[j * 2];
            s0a = fma2(wv.x, a0[2 * j],     s0a);
            s0b = fma2(wv.y, a0[2 * j + 1], s0b);
            s1a = fma2(wv.x, a1[2 * j],     s1a);
            s1b = fma2(wv.y, a1[2 * j + 1], s1b);
        }
        float2 u0a = unpack2(s0a), u0b = unpack2(s0b);
        float2 u1a = unpack2(s1a), u1b = unpack2(s1b);
        wcb[i * Qn + q0] = (u0a.x + u0a.y) + (u0b.x + u0b.y);
        wcb[i * Qn + q1] = (u1a.x + u1a.y) + (u1b.x + u1b.y);
    }
}

// ---------------- fused sentence path (persistent, 2 CTA/SM, cp.async) -------
// Y[o][q] = sum_i wS[i][o] * input[b][i][q],  wS[i][o] = w_sv[o][i]*sent[b][i]
// Tiles: TQ=128 q; block = 8 warps; warp owns 16 q; half-warp g owns 8 q
// (4 f32x2 pairs); lane&15 owns 8 output channels. acc = 4 pairs x 8 o.
// x tile cp.async'd raw in 4 chunks of 32 i (double buffered).
#define TQ 128
#define SGRID 304
#define SSMEM_BYTES (IDFn * 132 * 4 + 2 * 32 * TQ * 4)   // 67584+32768 = 100352

__global__ void __launch_bounds__(256, 2)
sent_kernel(const float* __restrict__ input,
            const float* __restrict__ w_sv,
            float* __restrict__ ws,
            float* __restrict__ sa) {
    extern __shared__ float smF[];
    float* wS = smF;                      // [128][132]
    float* xb = smF + IDFn * 132;         // [2][32][TQ]

    const int tid = threadIdx.x;
    const int w = tid >> 5, lane = tid & 31;
    const int hl = lane & 15, g = lane >> 4;
    const int obase = hl * 8;
    const int qsub = w * 16 + g * 8;

    // contiguous tile range for this block
    const int ntiles = Bn * (Qn / TQ);    // 2048
    const int base = ntiles / SGRID, rem = ntiles % SGRID;
    const int t0 = blockIdx.x * base + min(blockIdx.x, rem);
    const int cnt = base + (blockIdx.x < rem ? 1 : 0);
    const int totchunks = cnt * 4;

    auto kickS = [&](int gcv) {
        int t = t0 + (gcv >> 2);
        int c = gcv & 3;
        int bb = t >> 7;
        int qb = (t & 127) * TQ;
        const float* src = input + ((size_t)bb * IDFn + c * 32) * Qn + qb;
        float* dst = xb + (gcv & 1) * (32 * TQ);
#pragma unroll
        for (int j = 0; j < 4; j++) {
            int idx = j * 256 + tid;
            int r = idx >> 5, col = idx & 31;
            cpasync16(dst + r * TQ + col * 4, src + (size_t)r * Qn + col * 4);
        }
        CP_COMMIT();
    };

    if (cnt == 0) return;
    kickS(0);

    int bcur = -1;
    float sento[8];

    for (int tt = 0; tt < cnt; tt++) {
        const int t = t0 + tt;
        const int b = t >> 7;
        const int qbase = (t & 127) * TQ;

        if (b != bcur) {
            bcur = b;
            // previous tile's compute ended with a bar; safe to rewrite wS
            const float* sb = g_sent + b * IDFn;
            for (int idx = tid; idx < IDFn * IDFn; idx += 256) {
                int o = idx >> 7, i = idx & 127;
                wS[i * 132 + o] = w_sv[o * IDFn + i] * sb[i];
            }
#pragma unroll
            for (int oo = 0; oo < 8; oo++) sento[oo] = sb[obase + oo];
            __syncthreads();
        }

        unsigned long long acc[4][8];
#pragma unroll
        for (int p = 0; p < 4; p++)
#pragma unroll
            for (int oo = 0; oo < 8; oo++) acc[p][oo] = 0ULL;

        for (int c = 0; c < 4; c++) {
            const int cur = tt * 4 + c;
            if (cur + 1 < totchunks) { kickS(cur + 1); CP_WAIT1(); }
            else                     { CP_WAIT0(); }
            __syncthreads();
            const float* x = xb + (cur & 1) * (32 * TQ);
#pragma unroll 2
            for (int r = 0; r < 32; r++) {
                const int i = c * 32 + r;
                const float* wrow = &wS[i * 132 + obase];
                float4 wa4 = *(const float4*)wrow;
                float4 wb4 = *(const float4*)(wrow + 4);
                unsigned long long w2[8];
                w2[0] = pack2(wa4.x, wa4.x); w2[1] = pack2(wa4.y, wa4.y);
                w2[2] = pack2(wa4.z, wa4.z); w2[3] = pack2(wa4.w, wa4.w);
                w2[4] = pack2(wb4.x, wb4.x); w2[5] = pack2(wb4.y, wb4.y);
                w2[6] = pack2(wb4.z, wb4.z); w2[7] = pack2(wb4.w, wb4.w);
                const float* xr = &x[r * TQ + qsub];
                unsigned long long x0 = *(const unsigned long long*)(xr);
                unsigned long long x1 = *(const unsigned long long*)(xr + 2);
                unsigned long long x2 = *(const unsigned long long*)(xr + 4);
                unsigned long long x3 = *(const unsigned long long*)(xr + 6);
#pragma unroll
                for (int oo = 0; oo < 8; oo++) {
                    acc[0][oo] = fma2(w2[oo], x0, acc[0][oo]);
                    acc[1][oo] = fma2(w2[oo], x1, acc[1][oo]);
                    acc[2][oo] = fma2(w2[oo], x2, acc[2][oo]);
                    acc[3][oo] = fma2(w2[oo], x3, acc[3][oo]);
                }
            }
            __syncthreads();
        }

        // channel softmax per q (128 o spread over 16-lane half-warp)
#pragma unroll
        for (int p = 0; p < 4; p++) {
            float me = -3.0e38f, mo = -3.0e38f;
#pragma unroll
            for (int oo = 0; oo < 8; oo++) {
                float2 v = unpack2(acc[p][oo]);
                me = fmaxf(me, v.x); mo = fmaxf(mo, v.y);
            }
#pragma unroll
            for (int off = 1; off < 16; off <<= 1) {
                me = fmaxf(me, __shfl_xor_sync(0xffffffffu, me, off));
                mo = fmaxf(mo, __shfl_xor_sync(0xffffffffu, mo, off));
            }
            float ee[8], eo[8];
            float se = 0.0f, so = 0.0f;
#pragma unroll
            for (int oo = 0; oo < 8; oo++) {
                float2 v = unpack2(acc[p][oo]);
                ee[oo] = __expf(v.x - me); eo[oo] = __expf(v.y - mo);
                se += ee[oo]; so += eo[oo];
            }
#pragma unroll
            for (int off = 1; off < 16; off <<= 1) {
                se += __shfl_xor_sync(0xffffffffu, se, off);
                so += __shfl_xor_sync(0xffffffffu, so, off);
            }
            float re = 1.0f / se, ro = 1.0f / so;
#pragma unroll
            for (int oo = 0; oo < 8; oo++)
                acc[p][oo] = pack2(ee[oo] * re, eo[oo] * ro);
        }

        // direct register epilogue: 2x STG.128 per (oo, output)
        const size_t rowbase = ((size_t)b * IDFn + obase) * Qn + qbase + qsub;
#pragma unroll
        for (int oo = 0; oo < 8; oo++) {
            float2 c0 = unpack2(acc[0][oo]), c1 = unpack2(acc[1][oo]);
            float2 c2 = unpack2(acc[2][oo]), c3 = unpack2(acc[3][oo]);
            float4 v0 = make_float4(c0.x, c0.y, c1.x, c1.y);
            float4 v1 = make_float4(c2.x, c2.y, c3.x, c3.y);
            float s = sento[oo];
            float4 u0 = make_float4(v0.x * s, v0.y * s, v0.z * s, v0.w * s);
            float4 u1 = make_float4(v1.x * s, v1.y * s, v1.z * s, v1.w * s);
            float* sap = sa + rowbase + (size_t)oo * Qn;
            float* wsp = ws + rowbase + (size_t)oo * Qn;
            *(float4*)(sap)     = v0;
            *(float4*)(sap + 4) = v1;
            *(float4*)(wsp)     = u0;
            *(float4*)(wsp + 4) = u1;
        }
    }
}

// ---------------- launch ----------------
extern "C" void kernel_launch(void* const* d_in, const int* in_sizes, int n_in,
                              void* d_out, int out_size) {
    const float*         input    = (const float*)d_in[0];
    const float*         sentence = (const float*)d_in[1];
    const float*         context  = (const float*)d_in[2];
    const unsigned char* mask     = (const unsigned char*)d_in[3];
    const float*         w_ctx    = (const float*)d_in[4];
    const float*         w_sv     = (const float*)d_in[5];
    const float*         w_lin    = (const float*)d_in[6];
    const float*         b_lin    = (const float*)d_in[7];

    float* out = (float*)d_out;
    float* wc = out;                                    // (B,128,128,128)
    float* ws = out + (size_t)Bn * IDFn * Qn;           // (B,128,128,128)
    float* wa = ws + (size_t)Bn * IDFn * Qn;            // (B,48,128,128)
    float* sa = wa + (size_t)Bn * SLn * Qn;             // (B,128,128,128)

    prep_mask_kernel<<<1, Bn * SLn>>>(mask);
    prep_srcT_kernel<<<(Bn * IDFn * SLn) / 256, 256>>>(context, w_ctx);
    prep_sent_kernel<<<(Bn * IDFn) / 256, 256>>>(sentence, w_lin, b_lin);

    cudaFuncSetAttribute(attn_kernel,
                         cudaFuncAttributeMaxDynamicSharedMemorySize,
                         ASMEM_BYTES);
    attn_kernel<<<dim3(Qn / 512, Bn), 256, ASMEM_BYTES>>>(input, wc, wa);

    cudaFuncSetAttribute(sent_kernel,
                         cudaFuncAttributeMaxDynamicSharedMemorySize,
                         SSMEM_BYTES);
    sent_kernel<<<SGRID, 256, SSMEM_BYTES>>>(input, w_sv, ws, sa);
}

// round 9
// speedup vs baseline: 1.5162x; 1.0321x over previous
#include <cuda_runtime.h>

#define IDFn 128
#define CDFn 256
#define Bn   16
#define Qn   16384
#define SLn  48

// Scratch (no cudaMalloc allowed) — device globals.
__device__ __align__(16) float g_srcT[Bn * IDFn * SLn];   // [b][i][s]
__device__ __align__(16) float g_sent[Bn * IDFn];         // [b][o]
__device__ __align__(16) float g_maskF[Bn * SLn];         // 1.0 = masked

// ---------------- packed fp32x2 helpers ----------------
static __device__ __forceinline__ unsigned long long fma2(unsigned long long a,
                                                          unsigned long long b,
                                                          unsigned long long c) {
    unsigned long long d;
    asm("fma.rn.f32x2 %0, %1, %2, %3;" : "=l"(d) : "l"(a), "l"(b), "l"(c));
    return d;
}
static __device__ __forceinline__ unsigned long long pack2(float x, float y) {
    unsigned long long d;
    asm("mov.b64 %0, {%1, %2};" : "=l"(d) : "f"(x), "f"(y));
    return d;
}
static __device__ __forceinline__ float2 unpack2(unsigned long long v) {
    float2 r;
    asm("mov.b64 {%0, %1}, %2;" : "=f"(r.x), "=f"(r.y) : "l"(v));
    return r;
}
static __device__ __forceinline__ void cpasync16(void* sdst, const void* gsrc) {
    unsigned int sa = (unsigned int)__cvta_generic_to_shared(sdst);
    asm volatile("cp.async.cg.shared.global [%0], [%1], 16;" :: "r"(sa), "l"(gsrc));
}
#define CP_COMMIT() asm volatile("cp.async.commit_group;")
#define CP_WAIT1()  asm volatile("cp.async.wait_group 1;")
#define CP_WAIT0()  asm volatile("cp.async.wait_group 0;")

// ---------------- mask dtype detection + conversion ----------------
__global__ void prep_mask_kernel(const unsigned char* __restrict__ mraw) {
    __shared__ int cnt_f32, cnt_nz3;
    int tid = threadIdx.x;                 // 768 threads
    if (tid == 0) { cnt_f32 = 0; cnt_nz3 = 0; }
    __syncthreads();
    unsigned char v = mraw[tid];
    if (v == 0x3f || v == 0x80) atomicAdd(&cnt_f32, 1);
    if ((tid & 3) != 0 && v != 0) atomicAdd(&cnt_nz3, 1);
    __syncthreads();
    float f;
    if (cnt_f32 > 0) {
        f = (((const float*)mraw)[tid] != 0.0f) ? 1.0f : 0.0f;
    } else if (cnt_nz3 == 0) {
        f = ((const int*)mraw)[tid] ? 1.0f : 0.0f;
    } else {
        f = v ? 1.0f : 0.0f;
    }
    g_maskF[tid] = f;
}

// ---------------- prologue: sourceT = w_ctx @ context ----------------
__global__ void prep_srcT_kernel(const float* __restrict__ context,
                                 const float* __restrict__ w_ctx) {
    int idx = blockIdx.x * 256 + threadIdx.x;            // < 16*128*48
    int s = idx % SLn;
    int t = idx / SLn;
    int i = t % IDFn;
    int b = t / IDFn;
    const float* wr = w_ctx + i * CDFn;
    const float* cb = context + (b * CDFn) * SLn + s;
    float acc = 0.0f;
#pragma unroll 8
    for (int c = 0; c < CDFn; c++) acc = fmaf(wr[c], cb[c * SLn], acc);
    g_srcT[idx] = acc;
}

// ---------------- prologue: sent = sentence @ w_lin^T + b_lin ----------------
__global__ void prep_sent_kernel(const float* __restrict__ sentence,
                                 const float* __restrict__ w_lin,
                                 const float* __restrict__ b_lin) {
    int idx = blockIdx.x * 256 + threadIdx.x;            // < 16*128
    int o = idx % IDFn;
    int b = idx / IDFn;
    float acc = b_lin[o];
    const float* sb = sentence + b * 100;
    const float* wr = w_lin + o * 100;
#pragma unroll 4
    for (int j = 0; j < 100; j++) acc = fmaf(sb[j], wr[j], acc);
    g_sent[idx] = acc;
}

// ---------------- fused attention, 1 q/thread, 2 CTA/SM, cp.async ------------
#define ACHUNK 8
// sT 24576 + mS 256 + sIn 2*8*256*4 = 41216
#define ASMEM_BYTES (IDFn * 24 * 8 + 256 + 2 * ACHUNK * 256 * 4)

__global__ void __launch_bounds__(256, 2)
attn_kernel(const float* __restrict__ input,
            float* __restrict__ wc,
            float* __restrict__ wa) {
    extern __shared__ unsigned long long dynA[];
    unsigned long long* sT = dynA;                 // [128*24] ull
    float* mS  = (float*)(dynA + IDFn * 24);       // 64 floats (48 used)
    float* sIn = mS + 64;                          // [2][8][256] floats

    const int b = blockIdx.y;
    const int tid = threadIdx.x;
    const int qblk = blockIdx.x * 256;

    const unsigned long long* sg =
        (const unsigned long long*)(g_srcT + b * IDFn * SLn);
#pragma unroll
    for (int k = 0; k < 12; k++) sT[tid + k * 256] = sg[tid + k * 256];
    if (tid < SLn) mS[tid] = g_maskF[b * SLn + tid];

    const float* inb = input + (size_t)b * IDFn * Qn + qblk;

    // chunk kicker: 8 rows x 256 floats = 8KB, 2 x 16B per thread
    auto kick = [&](int c) {
        int buf = c & 1;
#pragma unroll
        for (int j = 0; j < 2; j++) {
            int idx = j * 256 + tid;
            int r = idx >> 6, col = idx & 63;
            cpasync16(&sIn[buf * (ACHUNK * 256) + r * 256 + col * 4],
                      inb + (c * ACHUNK + r) * Qn + col * 4);
        }
        CP_COMMIT();
    };

    kick(0);

    unsigned long long a0[24];
#pragma unroll
    for (int j = 0; j < 24; j++) a0[j] = 0ULL;

    // Phase A: logits[q][s] = sum_i target[i][q] * srcT[i][s]
    for (int c = 0; c < 16; c++) {
        if (c < 15) { kick(c + 1); CP_WAIT1(); }
        else        { CP_WAIT0(); }
        __syncthreads();
        const float* xb = sIn + (c & 1) * (ACHUNK * 256);
#pragma unroll
        for (int r = 0; r < ACHUNK; r++) {
            const int i = c * ACHUNK + r;
            float t0 = xb[r * 256 + tid];
            unsigned long long t0d = pack2(t0, t0);
            const unsigned long long* row = &sT[i * 24];
#pragma unroll
            for (int j = 0; j < 12; j++) {
                ulonglong2 wv = *(const ulonglong2*)&row[j * 2];
                a0[2 * j]     = fma2(wv.x, t0d, a0[2 * j]);
                a0[2 * j + 1] = fma2(wv.y, t0d, a0[2 * j + 1]);
            }
        }
        __syncthreads();
    }

    // masked softmax over 48 s-slots + store word_attn
    const int q0 = qblk + tid;
    {
        float* wab = wa + (size_t)b * SLn * Qn + q0;
        const float NEGINF = __int_as_float(0xff800000);
        float M = -3.0e38f;
#pragma unroll
        for (int j = 0; j < 24; j++) {
            float2 v = unpack2(a0[j]);
            if (mS[2 * j]     != 0.0f) v.x = NEGINF;
            if (mS[2 * j + 1] != 0.0f) v.y = NEGINF;
            a0[j] = pack2(v.x, v.y);
            M = fmaxf(M, fmaxf(v.x, v.y));
        }
        float S = 0.0f;
#pragma unroll
        for (int j = 0; j < 24; j++) {
            float2 v = unpack2(a0[j]);
            float e0 = __expf(v.x - M);
            float e1 = __expf(v.y - M);
            S += e0 + e1;
            a0[j] = pack2(e0, e1);
        }
        float r = 1.0f / S;
#pragma unroll
        for (int j = 0; j < 24; j++) {
            float2 v = unpack2(a0[j]);
            float p0 = v.x * r;
            float p1 = v.y * r;
            wab[(2 * j) * Qn]     = p0;
            wab[(2 * j + 1) * Qn] = p1;
            a0[j] = pack2(p0, p1);
        }
    }

    // Phase B: wc[i][q] = sum_s srcT[i][s] * p[q][s]
    float* wcb = wc + (size_t)b * IDFn * Qn + q0;
#pragma unroll 2
    for (int i = 0; i < 128; i++) {
        const unsigned long long* row = &sT[i * 24];
        unsigned long long s0a = 0ULL, s0b = 0ULL;
#pragma unroll
        for (int j = 0; j < 12; j++) {
            ulonglong2 wv = *(const ulonglong2*)&row[j * 2];
            s0a = fma2(wv.x, a0[2 * j],     s0a);
            s0b = fma2(wv.y, a0[2 * j + 1], s0b);
        }
        float2 u0a = unpack2(s0a), u0b = unpack2(s0b);
        wcb[i * Qn] = (u0a.x + u0a.y) + (u0b.x + u0b.y);
    }
}

// ---------------- fused sentence path (persistent, 2 CTA/SM, spill-free) -----
// Y[o][q] = sum_i wS[i][o] * input[b][i][q],  wS[i][o] = w_sv[o][i]*sent[b][i]
// TQ=64 q per tile; block = 8 warps; warp owns 8 q (4 f32x2 pairs);
// lane owns 4 output channels (lane*4..+3). acc = 4 pairs x 4 o = 16 ull.
#define TQ 64
#define SGRID 592
#define SSMEM_BYTES (IDFn * 132 * 4 + 2 * 32 * TQ * 4)   // 67584+16384 = 83968

__global__ void __launch_bounds__(256, 2)
sent_kernel(const float* __restrict__ input,
            const float* __restrict__ w_sv,
            float* __restrict__ ws,
            float* __restrict__ sa) {
    extern __shared__ float smF[];
    float* wS = smF;                      // [128][132]
    float* xb = smF + IDFn * 132;         // [2][32][TQ]

    const int tid = threadIdx.x;
    const int w = tid >> 5, lane = tid & 31;
    const int obase = lane * 4;
    const int qsub = w * 8;

    // contiguous tile range for this block
    const int ntiles = Bn * (Qn / TQ);    // 4096
    const int base = ntiles / SGRID, rem = ntiles % SGRID;
    const int t0 = blockIdx.x * base + min(blockIdx.x, rem);
    const int cnt = base + (blockIdx.x < rem ? 1 : 0);
    const int totchunks = cnt * 4;
    const int TPB = Qn / TQ;              // tiles per batch = 256

    auto kickS = [&](int gcv) {
        int t = t0 + (gcv >> 2);
        int c = gcv & 3;
        int bb = t / TPB;
        int qb = (t % TPB) * TQ;
        const float* src = input + ((size_t)bb * IDFn + c * 32) * Qn + qb;
        float* dst = xb + (gcv & 1) * (32 * TQ);
#pragma unroll
        for (int j = 0; j < 2; j++) {
            int idx = j * 256 + tid;
            int r = idx >> 4, col = idx & 15;
            cpasync16(dst + r * TQ + col * 4, src + (size_t)r * Qn + col * 4);
        }
        CP_COMMIT();
    };

    if (cnt == 0) return;
    kickS(0);

    int bcur = -1;
    float sento[4];

    for (int tt = 0; tt < cnt; tt++) {
        const int t = t0 + tt;
        const int b = t / TPB;
        const int qbase = (t % TPB) * TQ;

        if (b != bcur) {
            bcur = b;
            // all warps passed the chunk-loop barrier; safe to rewrite wS
            const float* sb = g_sent + b * IDFn;
            for (int idx = tid; idx < IDFn * IDFn; idx += 256) {
                int o = idx >> 7, i = idx & 127;
                wS[i * 132 + o] = w_sv[o * IDFn + i] * sb[i];
            }
#pragma unroll
            for (int oo = 0; oo < 4; oo++) sento[oo] = sb[obase + oo];
            __syncthreads();
        }

        unsigned long long acc[4][4];
#pragma unroll
        for (int p = 0; p < 4; p++)
#pragma unroll
            for (int oo = 0; oo < 4; oo++) acc[p][oo] = 0ULL;

        for (int c = 0; c < 4; c++) {
            const int cur = tt * 4 + c;
            if (cur + 1 < totchunks) { kickS(cur + 1); CP_WAIT1(); }
            else                     { CP_WAIT0(); }
            __syncthreads();
            const float* x = xb + (cur & 1) * (32 * TQ);
#pragma unroll 4
            for (int r = 0; r < 32; r++) {
                const int i = c * 32 + r;
                float4 w4 = *(const float4*)&wS[i * 132 + obase];
                unsigned long long w0 = pack2(w4.x, w4.x);
                unsigned long long w1 = pack2(w4.y, w4.y);
                unsigned long long w2v = pack2(w4.z, w4.z);
                unsigned long long w3 = pack2(w4.w, w4.w);
                const float* xr = &x[r * TQ + qsub];
                unsigned long long x0 = *(const unsigned long long*)(xr);
                unsigned long long x1 = *(const unsigned long long*)(xr + 2);
                unsigned long long x2 = *(const unsigned long long*)(xr + 4);
                unsigned long long x3 = *(const unsigned long long*)(xr + 6);
#pragma unroll
                for (int p = 0; p < 4; p++) {
                    unsigned long long xv = (p == 0) ? x0 : (p == 1) ? x1
                                          : (p == 2) ? x2 : x3;
                    acc[p][0] = fma2(w0,  xv, acc[p][0]);
                    acc[p][1] = fma2(w1,  xv, acc[p][1]);
                    acc[p][2] = fma2(w2v, xv, acc[p][2]);
                    acc[p][3] = fma2(w3,  xv, acc[p][3]);
                }
            }
            __syncthreads();
        }

        // channel softmax per q: 128 o spread as 4 per lane over 32 lanes
#pragma unroll
        for (int p = 0; p < 4; p++) {
            float me = -3.0e38f, mo = -3.0e38f;
#pragma unroll
            for (int oo = 0; oo < 4; oo++) {
                float2 v = unpack2(acc[p][oo]);
                me = fmaxf(me, v.x); mo = fmaxf(mo, v.y);
            }
#pragma unroll
            for (int off = 1; off < 32; off <<= 1) {
                me = fmaxf(me, __shfl_xor_sync(0xffffffffu, me, off));
                mo = fmaxf(mo, __shfl_xor_sync(0xffffffffu, mo, off));
            }
            float ee[4], eo[4];
            float se = 0.0f, so = 0.0f;
#pragma unroll
            for (int oo = 0; oo < 4; oo++) {
                float2 v = unpack2(acc[p][oo]);
                ee[oo] = __expf(v.x - me); eo[oo] = __expf(v.y - mo);
                se += ee[oo]; so += eo[oo];
            }
#pragma unroll
            for (int off = 1; off < 32; off <<= 1) {
                se += __shfl_xor_sync(0xffffffffu, se, off);
                so += __shfl_xor_sync(0xffffffffu, so, off);
            }
            float re = 1.0f / se, ro = 1.0f / so;
#pragma unroll
            for (int oo = 0; oo < 4; oo++)
                acc[p][oo] = pack2(ee[oo] * re, eo[oo] * ro);
        }

        // direct register epilogue: 2x STG.128 per (oo, output array)
        const size_t rowbase = ((size_t)b * IDFn + obase) * Qn + qbase + qsub;
#pragma unroll
        for (int oo = 0; oo < 4; oo++) {
            float2 c0 = unpack2(acc[0][oo]), c1 = unpack2(acc[1][oo]);
            float2 c2 = unpack2(acc[2][oo]), c3 = unpack2(acc[3][oo]);
            float4 v0 = make_float4(c0.x, c0.y, c1.x, c1.y);
            float4 v1 = make_float4(c2.x, c2.y, c3.x, c3.y);
            float s = sento[oo];
            float4 u0 = make_float4(v0.x * s, v0.y * s, v0.z * s, v0.w * s);
            float4 u1 = make_float4(v1.x * s, v1.y * s, v1.z * s, v1.w * s);
            float* sap = sa + rowbase + (size_t)oo * Qn;
            float* wsp = ws + rowbase + (size_t)oo * Qn;
            *(float4*)(sap)     = v0;
            *(float4*)(sap + 4) = v1;
            *(float4*)(wsp)     = u0;
            *(float4*)(wsp + 4) = u1;
        }
    }
}

// ---------------- launch ----------------
extern "C" void kernel_launch(void* const* d_in, const int* in_sizes, int n_in,
                              void* d_out, int out_size) {
    const float*         input    = (const float*)d_in[0];
    const float*         sentence = (const float*)d_in[1];
    const float*         context  = (const float*)d_in[2];
    const unsigned char* mask     = (const unsigned char*)d_in[3];
    const float*         w_ctx    = (const float*)d_in[4];
    const float*         w_sv     = (const float*)d_in[5];
    const float*         w_lin    = (const float*)d_in[6];
    const float*         b_lin    = (const float*)d_in[7];

    float* out = (float*)d_out;
    float* wc = out;                                    // (B,128,128,128)
    float* ws = out + (size_t)Bn * IDFn * Qn;           // (B,128,128,128)
    float* wa = ws + (size_t)Bn * IDFn * Qn;            // (B,48,128,128)
    float* sa = wa + (size_t)Bn * SLn * Qn;             // (B,128,128,128)

    prep_mask_kernel<<<1, Bn * SLn>>>(mask);
    prep_srcT_kernel<<<(Bn * IDFn * SLn) / 256, 256>>>(context, w_ctx);
    prep_sent_kernel<<<(Bn * IDFn) / 256, 256>>>(sentence, w_lin, b_lin);

    cudaFuncSetAttribute(attn_kernel,
                         cudaFuncAttributeMaxDynamicSharedMemorySize,
                         ASMEM_BYTES);
    attn_kernel<<<dim3(Qn / 256, Bn), 256, ASMEM_BYTES>>>(input, wc, wa);

    cudaFuncSetAttribute(sent_kernel,
                         cudaFuncAttributeMaxDynamicSharedMemorySize,
                         SSMEM_BYTES);
    sent_kernel<<<SGRID, 256, SSMEM_BYTES>>>(input, w_sv, ws, sa);
}